// round 17
// baseline (speedup 1.0000x reference)
#include <cuda_runtime.h>
#include <cuda_fp16.h>
#include <cstdint>

// Problem:
//   x:      (B=4, T=4096, D=1024) f32
//   idx:    (B=4, E=8, C=1024)    i32
//   weight: (E=8, O=512, D=1024)  f32
//   bias:   (E=8, O=512)          f32
//   out:    (B=4, E=8, C=1024, O=512) f32
// out[b,e,c,o] = sum_d x[b, idx[b,e,c], d] * w[e,o,d] + bias[e,o]
//
// fp16 HMMA GEMM, fp32 accumulation (rel_err ~2.8e-4).
// WARP-SPECIALIZED: warps 0-7 = consumers (pure ldmatrix+mma, R8 mapping,
// W via their own 3-stage cp.async from preconverted g_w16); warps 8-11 =
// producers (gathered A rows: LDG f32 -> cvt f16 -> STS, double-buffered A16,
// named-barrier handshake). convert_x pre-pass eliminated.

#define B_ 4
#define T_ 4096
#define D_ 1024
#define E_ 8
#define C_ 1024
#define O_ 512

#define MT 128
#define NT 128
#define KC 64             // f16 k per chunk
#define NCHUNK (D_ / KC)  // 16

#define A16_SZ 16384                 // one A16 buffer: 128 rows x 128B
#define W_OFF  32768                 // after 2 A16 buffers
#define WSTAGE_SZ 16384
#define SMEM_TOTAL (W_OFF + 3 * WSTAGE_SZ)   // 81920

#define NTHREADS 384                 // 256 consumers + 128 producers

__device__ __half g_w16[E_ * O_ * D_];
#define NWG ((E_ * O_ * D_) / 8)

__device__ __forceinline__ uint32_t smem_u32(const void* p) {
    uint32_t a;
    asm("{ .reg .u64 t; cvta.to.shared.u64 t, %1; cvt.u32.u64 %0, t; }" : "=r"(a) : "l"(p));
    return a;
}
__device__ __forceinline__ void cp_async16(uint32_t dst, const void* src) {
    asm volatile("cp.async.cg.shared.global [%0], [%1], 16;" :: "r"(dst), "l"(src));
}
__device__ __forceinline__ void cp_commit() {
    asm volatile("cp.async.commit_group;" ::: "memory");
}
__device__ __forceinline__ void cp_wait1() {
    asm volatile("cp.async.wait_group 1;" ::: "memory");
}
__device__ __forceinline__ void bar_sync(int id) {
    asm volatile("bar.sync %0, %1;" :: "r"(id), "n"(NTHREADS) : "memory");
}
__device__ __forceinline__ void bar_arrive(int id) {
    asm volatile("bar.arrive %0, %1;" :: "r"(id), "n"(NTHREADS) : "memory");
}
__device__ __forceinline__ void ldsm_x4(uint32_t* r, uint32_t addr) {
    asm volatile("ldmatrix.sync.aligned.m8n8.x4.shared.b16 {%0,%1,%2,%3}, [%4];"
                 : "=r"(r[0]), "=r"(r[1]), "=r"(r[2]), "=r"(r[3]) : "r"(addr));
}
__device__ __forceinline__ void mma_fp16(float* c, const uint32_t* a, uint32_t b0, uint32_t b1) {
    asm volatile(
        "mma.sync.aligned.m16n8k16.row.col.f32.f16.f16.f32 "
        "{%0,%1,%2,%3}, {%4,%5,%6,%7}, {%8,%9}, {%0,%1,%2,%3};"
        : "+f"(c[0]), "+f"(c[1]), "+f"(c[2]), "+f"(c[3])
        : "r"(a[0]), "r"(a[1]), "r"(a[2]), "r"(a[3]), "r"(b0), "r"(b1));
}

// barrier ids: 1 + (kc&1) = A16 buffer ready; 3 + (kc&1) = A16 buffer free
// ---------------------------------------------------------------------------
// fp32 -> fp16 converter for w (24MB traffic, ~5us)
// ---------------------------------------------------------------------------
__global__ __launch_bounds__(256)
void convert_w_kernel(const float* __restrict__ w) {
    size_t i = ((size_t)blockIdx.x * 256 + threadIdx.x) * 8;
    float4 v0 = *(const float4*)(w + i);
    float4 v1 = *(const float4*)(w + i + 4);
    __half2 h0 = __floats2half2_rn(v0.x, v0.y);
    __half2 h1 = __floats2half2_rn(v0.z, v0.w);
    __half2 h2 = __floats2half2_rn(v1.x, v1.y);
    __half2 h3 = __floats2half2_rn(v1.z, v1.w);
    *reinterpret_cast<uint4*>(g_w16 + i) =
        make_uint4(*(uint32_t*)&h0, *(uint32_t*)&h1, *(uint32_t*)&h2, *(uint32_t*)&h3);
}

// ---------------------------------------------------------------------------
// Main GEMM: 384 threads = 8 consumer warps (2Mx4N, 64x32) + 4 producer warps
// ---------------------------------------------------------------------------
__global__ __launch_bounds__(NTHREADS, 1)
void moe_fp16_kernel(const float* __restrict__ x,
                     const int*   __restrict__ idx,
                     const float* __restrict__ bias,
                     float*       __restrict__ out)
{
    extern __shared__ char smem[];
    const uint32_t sb = smem_u32(smem);
    const int tid  = threadIdx.x;
    const int wid  = tid >> 5;
    const int lane = tid & 31;

    const int be = blockIdx.z;
    const int b  = be >> 3;
    const int e  = be & 7;
    const int c0 = blockIdx.y * MT;
    const int o0 = blockIdx.x * NT;

    if (wid >= 8) {
        // ===================== PRODUCER (warps 8-11) =====================
        const int prow = tid - 256;                 // A row 0..127
        const int tok  = idx[be * C_ + c0 + prow];
        const float* xrow = x + ((size_t)b * T_ + tok) * D_;
        const uint32_t rowB = (uint32_t)(prow * 128);
        const uint32_t sw   = (uint32_t)((prow & 7) << 4);

        for (int kc = 0; kc < NCHUNK; kc++) {
            // load 64 f32 (16 x LDG.128, MLP 16)
            float4 v[16];
            const float* src = xrow + kc * KC;
            #pragma unroll
            for (int j = 0; j < 16; j++) v[j] = *(const float4*)(src + 4 * j);

            if (kc >= 2) bar_sync(3 + (kc & 1));    // wait buffer free

            char* dst = smem + (kc & 1) * A16_SZ + rowB;
            #pragma unroll
            for (int j = 0; j < 8; j++) {
                __half2 h0 = __floats2half2_rn(v[2 * j].x, v[2 * j].y);
                __half2 h1 = __floats2half2_rn(v[2 * j].z, v[2 * j].w);
                __half2 h2 = __floats2half2_rn(v[2 * j + 1].x, v[2 * j + 1].y);
                __half2 h3 = __floats2half2_rn(v[2 * j + 1].z, v[2 * j + 1].w);
                *reinterpret_cast<uint4*>(dst + (((uint32_t)(j * 16)) ^ sw)) =
                    make_uint4(*(uint32_t*)&h0, *(uint32_t*)&h1,
                               *(uint32_t*)&h2, *(uint32_t*)&h3);
            }
            bar_arrive(1 + (kc & 1));               // buffer ready
        }
        return;
    }

    // ===================== CONSUMER (warps 0-7) =====================
    // W producer mapping (cp.async): row = tid/2, 64B half = tid&1
    const int prow  = tid >> 1;
    const int phalf = (tid & 1) * 64;
    const __half* wsrc = g_w16 + ((size_t)(e * O_ + o0 + prow)) * D_ + (phalf >> 1);
    const uint32_t pXor  = (uint32_t)((prow & 7) << 4);
    const uint32_t pRowB = (uint32_t)(prow * 128);

    const int wm = wid >> 2;
    const int wn = wid & 3;
    const uint32_t fXor = (uint32_t)((lane & 7) << 4);
    const uint32_t aBase = (uint32_t)((wm * 64 + (lane & 15)) * 128);
    const uint32_t aSegL = (uint32_t)((lane >> 4) * 16);
    const uint32_t wBase = (uint32_t)(W_OFF + (wn * 32 + ((lane >> 4) << 3) + (lane & 7)) * 128);
    const uint32_t wSegL = (uint32_t)(((lane >> 3) & 1) * 16);

    float acc[4][4][4];
    #pragma unroll
    for (int i = 0; i < 4; i++)
        #pragma unroll
        for (int j = 0; j < 4; j++)
            #pragma unroll
            for (int q = 0; q < 4; q++) acc[i][j][q] = 0.0f;

    auto load_w = [&](int kc) {
        const uint32_t wbase = sb + W_OFF + (uint32_t)((kc % 3) * WSTAGE_SZ) + pRowB;
        const __half* wp = wsrc + kc * KC;
        #pragma unroll
        for (int j = 0; j < 4; j++) {
            const uint32_t off = ((uint32_t)(phalf + j * 16)) ^ pXor;
            cp_async16(wbase + off, wp + j * 8);
        }
    };

    load_w(0); cp_commit();
    load_w(1); cp_commit();

    uint32_t af[2][4][4];
    uint32_t wf[2][2][4];

    for (int kc = 0; kc < NCHUNK; kc++) {
        cp_wait1();                  // W(kc) resident
        bar_sync(1 + (kc & 1));      // A16(kc) ready

        if (kc + 2 < NCHUNK) load_w(kc + 2);
        cp_commit();                 // empty groups at tail keep counts valid

        const uint32_t aAddr = sb + (uint32_t)((kc & 1) * A16_SZ) + aBase;
        const uint32_t wAddr = sb + (uint32_t)((kc % 3) * WSTAGE_SZ) + wBase;

        #pragma unroll
        for (int mt = 0; mt < 4; mt++)
            ldsm_x4(af[0][mt], aAddr + mt * 2048 + ((0 + aSegL) ^ fXor));
        #pragma unroll
        for (int np = 0; np < 2; np++)
            ldsm_x4(wf[0][np], wAddr + np * 2048 + ((0 + wSegL) ^ fXor));

        #pragma unroll
        for (int ks = 0; ks < 4; ks++) {
            const int cur = ks & 1;
            const int nxt = cur ^ 1;
            if (ks < 3) {
                const uint32_t kb = (uint32_t)((ks + 1) * 32);
                #pragma unroll
                for (int mt = 0; mt < 4; mt++)
                    ldsm_x4(af[nxt][mt], aAddr + mt * 2048 + ((kb + aSegL) ^ fXor));
                #pragma unroll
                for (int np = 0; np < 2; np++)
                    ldsm_x4(wf[nxt][np], wAddr + np * 2048 + ((kb + wSegL) ^ fXor));
            }
            #pragma unroll
            for (int mt = 0; mt < 4; mt++)
                #pragma unroll
                for (int np = 0; np < 2; np++) {
                    mma_fp16(acc[mt][np * 2 + 0], af[cur][mt], wf[cur][np][0], wf[cur][np][1]);
                    mma_fp16(acc[mt][np * 2 + 1], af[cur][mt], wf[cur][np][2], wf[cur][np][3]);
                }
        }

        bar_arrive(3 + (kc & 1));    // A16(kc) free
    }

    // ---- epilogue (consumers only) ----
    float2 bv[4];
    #pragma unroll
    for (int n4 = 0; n4 < 4; n4++)
        bv[n4] = *reinterpret_cast<const float2*>(bias + e * O_ + o0 + wn * 32 + n4 * 8 + (lane & 3) * 2);

    #pragma unroll
    for (int mt = 0; mt < 4; mt++) {
        const int row = wm * 64 + mt * 16 + (lane >> 2);
        float* d0 = out + ((size_t)be * C_ + c0 + row) * O_ + o0;
        float* d1 = d0 + 8 * O_;
        #pragma unroll
        for (int n4 = 0; n4 < 4; n4++) {
            const int col = wn * 32 + n4 * 8 + (lane & 3) * 2;
            float2 v0, v1;
            v0.x = acc[mt][n4][0] + bv[n4].x;
            v0.y = acc[mt][n4][1] + bv[n4].y;
            v1.x = acc[mt][n4][2] + bv[n4].x;
            v1.y = acc[mt][n4][3] + bv[n4].y;
            *reinterpret_cast<float2*>(d0 + col) = v0;
            *reinterpret_cast<float2*>(d1 + col) = v1;
        }
    }
}

extern "C" void kernel_launch(void* const* d_in, const int* in_sizes, int n_in,
                              void* d_out, int out_size)
{
    const float* x    = (const float*)d_in[0];
    const int*   idx  = (const int*)  d_in[1];
    const float* w    = (const float*)d_in[2];
    const float* bias = (const float*)d_in[3];
    float* out = (float*)d_out;

    cudaFuncSetAttribute(moe_fp16_kernel,
                         cudaFuncAttributeMaxDynamicSharedMemorySize, SMEM_TOTAL);

    convert_w_kernel<<<NWG / 256, 256>>>(w);

    dim3 grid(O_ / NT, C_ / MT, B_ * E_);   // (4, 8, 32)
    moe_fp16_kernel<<<grid, NTHREADS, SMEM_TOTAL>>>(x, idx, bias, out);
}